// round 5
// baseline (speedup 1.0000x reference)
#include <cuda_runtime.h>

// Problem constants (fixed by the reference: B=4, C=32, H=64, W=64, NW=64)
#define NWC 64
#define NPAIR 32
#define HW_PIX 4096
#define CC 32

// Packed f32x2 FMA: d = a*b + c on two fp32 lanes in one FFMA2 instruction.
__device__ __forceinline__ void ffma2(float& dx, float& dy,
                                      float ax, float ay,
                                      float bx, float by,
                                      float cx, float cy) {
    asm("{\n\t"
        ".reg .b64 ra, rb, rc, rd;\n\t"
        "mov.b64 ra, {%2, %3};\n\t"
        "mov.b64 rb, {%4, %5};\n\t"
        "mov.b64 rc, {%6, %7};\n\t"
        "fma.rn.f32x2 rd, ra, rb, rc;\n\t"
        "mov.b64 {%0, %1}, rd;\n\t"
        "}"
        : "=f"(dx), "=f"(dy)
        : "f"(ax), "f"(ay), "f"(bx), "f"(by), "f"(cx), "f"(cy));
}

__device__ __forceinline__ float ex2(float a) {
    float r;
    asm("ex2.approx.ftz.f32 %0, %1;" : "=f"(r) : "f"(a));
    return r;
}

__global__ __launch_bounds__(128)
void cplx_gaussian_rbf_kernel(
    const float* __restrict__ x_real, const float* __restrict__ x_imag,
    const float* __restrict__ w_real, const float* __restrict__ w_imag,
    const float* __restrict__ b_real, const float* __restrict__ b_imag,
    const float* __restrict__ mu_real, const float* __restrict__ mu_imag,
    const float* __restrict__ stddev,
    float* __restrict__ out)
{
    // Center-pair coefficient tables: f32x2 lanes carry (center 2p, center 2p+1),
    // so no duplication is needed and 3 LDS.128 serve TWO centers.
    __shared__ float4 sA[NPAIR];  // {a0_e, a0_o, a1_e, a1_o}
    __shared__ float4 sB[NPAIR];  // {a2_e, a2_o, a3_e, a3_o}
    __shared__ float4 sW[NPAIR];  // {wr_e, wr_o, wi_e, wi_o}

    const int bc   = blockIdx.x >> 4;        // (b*C + c), 0..127
    const int tile = blockIdx.x & 15;        // 16 tiles of 256 pixels per (b,c)
    const int c    = bc & (CC - 1);
    const int tid  = threadIdx.x;

    if (tid < NPAIR) {
        const float LOG2E = 1.4426950408889634f;
        const int n0 = 2 * tid, n1 = 2 * tid + 1;
        // exp(-d2/(2*sigma)) = exp2( a0*s + a1*xr + a2*xi + a3 ),  s = xr^2+xi^2
        float mur0 = mu_real[n0], mui0 = mu_imag[n0];
        float cc0  = LOG2E * 0.5f / stddev[n0];
        float mur1 = mu_real[n1], mui1 = mu_imag[n1];
        float cc1  = LOG2E * 0.5f / stddev[n1];
        sA[tid] = make_float4(-cc0, -cc1, 2.0f * cc0 * mur0, 2.0f * cc1 * mur1);
        sB[tid] = make_float4(2.0f * cc0 * mui0, 2.0f * cc1 * mui1,
                              -cc0 * (mur0 * mur0 + mui0 * mui0),
                              -cc1 * (mur1 * mur1 + mui1 * mui1));
        sW[tid] = make_float4(w_real[c * NWC + n0], w_real[c * NWC + n1],
                              w_imag[c * NWC + n0], w_imag[c * NWC + n1]);
    }
    __syncthreads();

    // 2 consecutive pixels per thread (one float2 load each input).
    const int pairIdx = bc * (HW_PIX / 2) + tile * 128 + tid;  // pixel-pair units
    const float2 xr = reinterpret_cast<const float2*>(x_real)[pairIdx];
    const float2 xi = reinterpret_cast<const float2*>(x_imag)[pairIdx];

    const float s0 = fmaf(xr.x, xr.x, xi.x * xi.x);
    const float s1 = fmaf(xr.y, xr.y, xi.y * xi.y);

    // f32x2 accumulators: lane0 = even centers, lane1 = odd centers.
    float ar0x = 0.0f, ar0y = 0.0f, ai0x = 0.0f, ai0y = 0.0f;  // pixel 0
    float ar1x = 0.0f, ar1y = 0.0f, ai1x = 0.0f, ai1y = 0.0f;  // pixel 1

#pragma unroll 8
    for (int p = 0; p < NPAIR; ++p) {
        const float4 A  = sA[p];
        const float4 Bv = sB[p];
        const float4 Wv = sW[p];

        // pixel 0
        float g0x, g0y;
        ffma2(g0x, g0y, s0,   s0,   A.x,  A.y,  Bv.z, Bv.w);  // a0*s + a3
        ffma2(g0x, g0y, xr.x, xr.x, A.z,  A.w,  g0x,  g0y);   // + a1*xr
        ffma2(g0x, g0y, xi.x, xi.x, Bv.x, Bv.y, g0x,  g0y);   // + a2*xi
        float r0x = ex2(g0x);
        float r0y = ex2(g0y);
        ffma2(ar0x, ar0y, r0x, r0y, Wv.x, Wv.y, ar0x, ar0y);
        ffma2(ai0x, ai0y, r0x, r0y, Wv.z, Wv.w, ai0x, ai0y);

        // pixel 1
        float g1x, g1y;
        ffma2(g1x, g1y, s1,   s1,   A.x,  A.y,  Bv.z, Bv.w);
        ffma2(g1x, g1y, xr.y, xr.y, A.z,  A.w,  g1x,  g1y);
        ffma2(g1x, g1y, xi.y, xi.y, Bv.x, Bv.y, g1x,  g1y);
        float r1x = ex2(g1x);
        float r1y = ex2(g1y);
        ffma2(ar1x, ar1y, r1x, r1y, Wv.x, Wv.y, ar1x, ar1y);
        ffma2(ai1x, ai1y, r1x, r1y, Wv.z, Wv.w, ai1x, ai1y);
    }

    const float br = b_real[c];
    const float bi = b_imag[c];

    // Horizontal add (even+odd centers) + bias; one float4 store (r0,i0,r1,i1).
    float4 o;
    o.x = (ar0x + ar0y) + br;
    o.y = (ai0x + ai0y) + bi;
    o.z = (ar1x + ar1y) + br;
    o.w = (ai1x + ai1y) + bi;
    reinterpret_cast<float4*>(out)[pairIdx] = o;
}

extern "C" void kernel_launch(void* const* d_in, const int* in_sizes, int n_in,
                              void* d_out, int out_size) {
    const float* x_real  = (const float*)d_in[0];
    const float* x_imag  = (const float*)d_in[1];
    const float* w_real  = (const float*)d_in[2];
    const float* w_imag  = (const float*)d_in[3];
    const float* b_real  = (const float*)d_in[4];
    const float* b_imag  = (const float*)d_in[5];
    const float* mu_real = (const float*)d_in[6];
    const float* mu_imag = (const float*)d_in[7];
    const float* stddev  = (const float*)d_in[8];
    float* out = (float*)d_out;

    // 128 (b,c) pairs * 16 tiles = 2048 blocks; 128 threads; 2 pixels/thread
    cplx_gaussian_rbf_kernel<<<2048, 128>>>(
        x_real, x_imag, w_real, w_imag, b_real, b_imag,
        mu_real, mu_imag, stddev, out);
}